// round 6
// baseline (speedup 1.0000x reference)
#include <cuda_runtime.h>
#include <cuda_bf16.h>
#include <cstdint>
#include <cstddef>

// Problem constants
#define BB   512
#define AA   100
#define HH   1024
#define INN  77          // S*T = 7*11
#define GG   4096        // 4*H
#define M1   (AA*BB)     // 51200
#define BH   (BB*HH)     // 524288

typedef __nv_bfloat16 bf16;

// ---------------- scratch (device globals; no allocation allowed) ----------------
__device__ float g_xr    [(size_t)M1 * INN];   // reordered inputs [A*B, 77]
__device__ bf16  g_ehi   [(size_t)M1 * HH];    // embedded hi (bf16)
__device__ bf16  g_elo   [(size_t)M1 * HH];    // embedded lo (bf16)
__device__ float g_gx    [(size_t)M1 * GG];    // input gates, gate-interleaved cols
__device__ bf16  g_hhi   [BH];
__device__ bf16  g_hlo   [BH];
__device__ float g_c     [BH];
__device__ float g_bias  [GG];                 // gate-interleaved
__device__ bf16  g_wih_hi[(size_t)GG * HH];    // rows gate-interleaved
__device__ bf16  g_wih_lo[(size_t)GG * HH];
__device__ bf16  g_whh_hi[(size_t)GG * HH];
__device__ bf16  g_whh_lo[(size_t)GG * HH];

// ================= PTX helpers (sm_80+ standard; NO arch-'a' features) =========
__device__ __forceinline__ uint32_t smem_u32(const void* p) {
    uint32_t a;
    asm("{ .reg .u64 t; cvta.to.shared.u64 t, %1; cvt.u32.u64 %0, t; }" : "=r"(a) : "l"(p));
    return a;
}
#define SMEM_SWIZZLE_128B(o) ((o) ^ (((o) >> 3) & 0x70))

__device__ __forceinline__ void cp_async16(uint32_t smem_addr, const void* gptr) {
    asm volatile("cp.async.cg.shared.global [%0], [%1], 16;"
                 :: "r"(smem_addr), "l"(gptr) : "memory");
}
#define CP_COMMIT() asm volatile("cp.async.commit_group;" ::: "memory")
#define CP_WAIT(n)  asm volatile("cp.async.wait_group %0;" :: "n"(n) : "memory")

__device__ __forceinline__ void ldsm_x4(uint32_t addr, uint32_t& r0, uint32_t& r1,
                                        uint32_t& r2, uint32_t& r3) {
    asm volatile("ldmatrix.sync.aligned.m8n8.x4.shared.b16 {%0,%1,%2,%3}, [%4];"
                 : "=r"(r0), "=r"(r1), "=r"(r2), "=r"(r3) : "r"(addr));
}

__device__ __forceinline__ void mma_bf16(float* d, const uint32_t* a, const uint32_t* b) {
    asm volatile(
        "mma.sync.aligned.m16n8k16.row.col.f32.bf16.bf16.f32 "
        "{%0,%1,%2,%3}, {%4,%5,%6,%7}, {%8,%9}, {%0,%1,%2,%3};"
        : "+f"(d[0]), "+f"(d[1]), "+f"(d[2]), "+f"(d[3])
        : "r"(a[0]), "r"(a[1]), "r"(a[2]), "r"(a[3]), "r"(b[0]), "r"(b[1]));
}

// ================= prep kernels =================
__global__ void reorder_kernel(const float* __restrict__ inputs) {
    int idx = blockIdx.x * blockDim.x + threadIdx.x;
    if (idx >= M1 * INN) return;
    int i = idx % INN;
    int r = idx / INN;        // r = a*B + b
    int b = r % BB;
    int a = r / BB;
    g_xr[idx] = inputs[(size_t)b * (AA * INN) + (size_t)a * INN + i];
}

// bias, gate-interleaved: dst[(hh<<2)|gate] = b_ih[j]+b_hh[j], j = gate*1024+hh
__global__ void bias_init_kernel(const float* __restrict__ b_ih, const float* __restrict__ b_hh) {
    int j = blockIdx.x * blockDim.x + threadIdx.x;
    if (j >= GG) return;
    int gate = j >> 10, hh = j & 1023;
    g_bias[(hh << 2) | gate] = b_ih[j] + b_hh[j];
}

__global__ void state_init_kernel(const float* __restrict__ h0, const float* __restrict__ c0) {
    int i = blockIdx.x * blockDim.x + threadIdx.x;
    if (i >= BH) return;
    float h = h0[i];
    bf16 hb = __float2bfloat16(h);
    g_hhi[i] = hb;
    g_hlo[i] = __float2bfloat16(h - __bfloat162float(hb));
    g_c[i] = c0[i];
}

// W decomp with gate-interleaved row permutation
__global__ void decomp_perm_kernel(const float* __restrict__ src, bf16* __restrict__ hi,
                                   bf16* __restrict__ lo) {
    int i = blockIdx.x * blockDim.x + threadIdx.x;
    if (i >= GG * HH) return;
    int j = i >> 10;          // original row (0..4095)
    int k = i & 1023;         // col
    int gate = j >> 10, hh = j & 1023;
    size_t dst = ((size_t)((hh << 2) | gate)) * HH + k;
    float v = src[i];
    bf16 hb = __float2bfloat16(v);
    hi[dst] = hb;
    lo[dst] = __float2bfloat16(v - __bfloat162float(hb));
}

// ============ SIMT SGEMM for embedding (K=77) -> bf16 hi/lo ============
template<int BM, int BN, int BK, int TM, int TN>
__global__ __launch_bounds__((BM/TM)*(BN/TN))
void sgemm_nt_hilo(const float* __restrict__ A, const float* __restrict__ Bm,
                   const float* __restrict__ bias, bf16* __restrict__ Chi,
                   bf16* __restrict__ Clo, int M, int N, int K) {
    __shared__ float As[BK][BM];
    __shared__ float Bs[BK][BN];
    constexpr int NTHREADS = (BM/TM)*(BN/TN);
    const int tid = threadIdx.x;
    const int tx = tid % (BN/TN);
    const int ty = tid / (BN/TN);
    const float* Ab = A + (size_t)blockIdx.y * BM * K;
    const float* Bb = Bm + (size_t)blockIdx.x * BN * K;

    float acc[TM][TN];
    #pragma unroll
    for (int i = 0; i < TM; i++)
        #pragma unroll
        for (int j = 0; j < TN; j++) acc[i][j] = 0.f;

    for (int k0 = 0; k0 < K; k0 += BK) {
        #pragma unroll
        for (int i = tid; i < BM * BK; i += NTHREADS) {
            int m = i / BK, k = i % BK;
            As[k][m] = (k0 + k < K) ? Ab[(size_t)m * K + k0 + k] : 0.f;
        }
        #pragma unroll
        for (int i = tid; i < BN * BK; i += NTHREADS) {
            int n = i / BK, k = i % BK;
            Bs[k][n] = (k0 + k < K) ? Bb[(size_t)n * K + k0 + k] : 0.f;
        }
        __syncthreads();
        #pragma unroll
        for (int k = 0; k < BK; k++) {
            float a[TM], b[TN];
            #pragma unroll
            for (int i = 0; i < TM; i++) a[i] = As[k][ty * TM + i];
            #pragma unroll
            for (int j = 0; j < TN; j++) b[j] = Bs[k][tx * TN + j];
            #pragma unroll
            for (int i = 0; i < TM; i++)
                #pragma unroll
                for (int j = 0; j < TN; j++)
                    acc[i][j] = fmaf(a[i], b[j], acc[i][j]);
        }
        __syncthreads();
    }

    #pragma unroll
    for (int i = 0; i < TM; i++) {
        size_t m = (size_t)blockIdx.y * BM + ty * TM + i;
        #pragma unroll
        for (int j = 0; j < TN; j++) {
            int n = blockIdx.x * BN + tx * TN + j;
            float v = acc[i][j] + bias[n];
            bf16 hb = __float2bfloat16(v);
            Chi[m * N + n] = hb;
            Clo[m * N + n] = __float2bfloat16(v - __bfloat162float(hb));
        }
    }
}

// ================= R4-style 3-pass bf16-split GEMM (for gx; 2 CTAs/SM) =========
// C[M,N] = A*B^T where A = Ahi+Alo, B = Bhi+Blo (bf16 pairs), fp32 accum.
// 3 passes over K: (Ahi,Bhi), (Ahi,Blo), (Alo,Bhi). AlBl dropped (~2^-18).
// CTA tile 128x128, 8 warps (2x4), warp tile 64x32, K-chunk 64, cp.async 2-stage.
#define CHUNK3P 64
#define OPT3P_BYTES 16384               // 128 rows * 128 bytes
#define STAGE3P_BYTES (2 * OPT3P_BYTES)
#define SMEM_3P_BYTES (2 * STAGE3P_BYTES + 1024)

__global__ __launch_bounds__(256, 2)
void mma_gemm_3p(const bf16* __restrict__ Ahi, const bf16* __restrict__ Alo,
                 const bf16* __restrict__ Bhi, const bf16* __restrict__ Blo,
                 const float* __restrict__ bias, float* __restrict__ C,
                 int K, int ldc) {
    extern __shared__ char sm[];
    const uint32_t base = (smem_u32(sm) + 1023u) & ~1023u;
    const int tid = threadIdx.x;
    const int wid = tid >> 5, lane = tid & 31;
    const int wm = (wid >> 2) * 64;
    const int wn = (wid & 3) * 32;

    const int cpp = K / CHUNK3P;
    const int total = 3 * cpp;

    const bf16* Aps[3] = {Ahi, Ahi, Alo};
    const bf16* Bps[3] = {Bhi, Blo, Bhi};

    float acc[4][4][4];
    #pragma unroll
    for (int mi = 0; mi < 4; mi++)
        #pragma unroll
        for (int nj = 0; nj < 4; nj++)
            #pragma unroll
            for (int q = 0; q < 4; q++) acc[mi][nj][q] = 0.f;

    auto prefetch = [&](int ch) {
        const int p = ch / cpp;
        const int kc = (ch % cpp) * CHUNK3P;
        const bf16* Ab = Aps[p] + (size_t)blockIdx.y * 128 * K + kc;
        const bf16* Bb = Bps[p] + (size_t)blockIdx.x * 128 * K + kc;
        const uint32_t sA = base + (uint32_t)(ch & 1) * STAGE3P_BYTES;
        const uint32_t sB = sA + OPT3P_BYTES;
        #pragma unroll
        for (int it = 0; it < 4; it++) {
            const int idx = it * 256 + tid;       // 0..1023
            const int row = idx >> 3;
            const int c8  = idx & 7;
            const uint32_t off = SMEM_SWIZZLE_128B((uint32_t)(row * 128 + c8 * 16));
            cp_async16(sA + off, Ab + (size_t)row * K + c8 * 8);
            cp_async16(sB + off, Bb + (size_t)row * K + c8 * 8);
        }
    };

    prefetch(0);
    CP_COMMIT();

    const int tsel = lane >> 3, rin = lane & 7;

    for (int ch = 0; ch < total; ch++) {
        if (ch + 1 < total) {
            prefetch(ch + 1);
            CP_COMMIT();
            CP_WAIT(1);
        } else {
            CP_WAIT(0);
        }
        __syncthreads();

        const uint32_t sA = base + (uint32_t)(ch & 1) * STAGE3P_BYTES;
        const uint32_t sB = sA + OPT3P_BYTES;

        #pragma unroll
        for (int kk = 0; kk < CHUNK3P; kk += 16) {
            const int col = kk + (tsel >> 1) * 8;
            uint32_t a[4][4];
            #pragma unroll
            for (int mi = 0; mi < 4; mi++) {
                const int row = wm + mi * 16 + (tsel & 1) * 8 + rin;
                const uint32_t addr = sA + SMEM_SWIZZLE_128B((uint32_t)(row * 128 + col * 2));
                ldsm_x4(addr, a[mi][0], a[mi][1], a[mi][2], a[mi][3]);
            }
            uint32_t b[4][2];
            #pragma unroll
            for (int g = 0; g < 2; g++) {
                const int row = wn + g * 16 + (tsel & 1) * 8 + rin;
                const uint32_t addr = sB + SMEM_SWIZZLE_128B((uint32_t)(row * 128 + col * 2));
                uint32_t r0, r1, r2, r3;
                ldsm_x4(addr, r0, r1, r2, r3);
                b[g * 2 + 0][0] = r0; b[g * 2 + 0][1] = r2;
                b[g * 2 + 1][0] = r1; b[g * 2 + 1][1] = r3;
            }
            #pragma unroll
            for (int mi = 0; mi < 4; mi++)
                #pragma unroll
                for (int nj = 0; nj < 4; nj++)
                    mma_bf16(acc[mi][nj], a[mi], b[nj]);
        }
        __syncthreads();
    }

    // epilogue
    const int r0 = lane >> 2;
    const int c0 = (lane & 3) * 2;
    #pragma unroll
    for (int mi = 0; mi < 4; mi++) {
        const size_t m0 = (size_t)blockIdx.y * 128 + wm + mi * 16;
        #pragma unroll
        for (int nj = 0; nj < 4; nj++) {
            const int n = blockIdx.x * 128 + wn + nj * 8 + c0;
            float bx = 0.f, by = 0.f;
            if (bias) { bx = bias[n]; by = bias[n + 1]; }
            float2 v0 = make_float2(acc[mi][nj][0] + bx, acc[mi][nj][1] + by);
            float2 v1 = make_float2(acc[mi][nj][2] + bx, acc[mi][nj][3] + by);
            *(float2*)(C + (m0 + r0) * (size_t)ldc + n) = v0;
            *(float2*)(C + (m0 + r0 + 8) * (size_t)ldc + n) = v1;
        }
    }
}

// ====== R5-style fused recurrent GEMM + LSTM cell (128 CTAs; 192KB smem OK) ======
// gh = (hhi+hlo) @ (Whh_hi+Whh_lo)^T fused in one K-loop; cell in epilogue.
#define CHUNK 64
#define KDIM 1024
#define NCHUNK (KDIM / CHUNK)
#define OPT_BYTES 16384                 // one 128x64 bf16 tile
#define STAGE_BYTES (4 * OPT_BYTES)     // Ahi, Alo, Bhi, Blo
#define NSTAGE 3
#define SMEM_FUSED_BYTES (NSTAGE * STAGE_BYTES + 1024)

__global__ __launch_bounds__(256, 1)
void mma_gemm_cell(const bf16* __restrict__ Ahi, const bf16* __restrict__ Alo,
                   const bf16* __restrict__ Bhi, const bf16* __restrict__ Blo,
                   const float* __restrict__ gx, float* __restrict__ c_state,
                   bf16* __restrict__ hhi, bf16* __restrict__ hlo,
                   float* __restrict__ out_t) {
    extern __shared__ char sm[];
    const uint32_t base = (smem_u32(sm) + 1023u) & ~1023u;
    const int tid = threadIdx.x;
    const int wid = tid >> 5, lane = tid & 31;
    const int wm = (wid >> 2) * 64;
    const int wn = (wid & 3) * 32;

    const bf16* Ahi_b = Ahi + (size_t)blockIdx.y * 128 * KDIM;
    const bf16* Alo_b = Alo + (size_t)blockIdx.y * 128 * KDIM;
    const bf16* Bhi_b = Bhi + (size_t)blockIdx.x * 128 * KDIM;
    const bf16* Blo_b = Blo + (size_t)blockIdx.x * 128 * KDIM;

    float acc[4][4][4];
    #pragma unroll
    for (int mi = 0; mi < 4; mi++)
        #pragma unroll
        for (int nj = 0; nj < 4; nj++)
            #pragma unroll
            for (int q = 0; q < 4; q++) acc[mi][nj][q] = 0.f;

    auto prefetch = [&](int ch) {
        const int kc = ch * CHUNK;
        const uint32_t st = base + (uint32_t)(ch % NSTAGE) * STAGE_BYTES;
        #pragma unroll
        for (int it = 0; it < 4; it++) {
            const int idx = it * 256 + tid;       // 0..1023
            const int row = idx >> 3;
            const int c8  = idx & 7;
            const uint32_t off = SMEM_SWIZZLE_128B((uint32_t)(row * 128 + c8 * 16));
            const size_t go = (size_t)row * KDIM + kc + c8 * 8;
            cp_async16(st + off,                 Ahi_b + go);
            cp_async16(st + OPT_BYTES + off,     Alo_b + go);
            cp_async16(st + 2 * OPT_BYTES + off, Bhi_b + go);
            cp_async16(st + 3 * OPT_BYTES + off, Blo_b + go);
        }
    };

    prefetch(0); CP_COMMIT();
    prefetch(1); CP_COMMIT();

    const int tsel = lane >> 3, rin = lane & 7;

    for (int ch = 0; ch < NCHUNK; ch++) {
        if (ch + 2 < NCHUNK) {
            prefetch(ch + 2);
            CP_COMMIT();
            CP_WAIT(2);
        } else {
            CP_WAIT(0);
        }
        __syncthreads();

        const uint32_t st = base + (uint32_t)(ch % NSTAGE) * STAGE_BYTES;
        const uint32_t sAh = st, sAl = st + OPT_BYTES;
        const uint32_t sBh = st + 2 * OPT_BYTES, sBl = st + 3 * OPT_BYTES;

        #pragma unroll
        for (int kk = 0; kk < CHUNK; kk += 16) {
            const int col = kk + (tsel >> 1) * 8;
            uint32_t ah[4][4], al[4][4];
            #pragma unroll
            for (int mi = 0; mi < 4; mi++) {
                const int row = wm + mi * 16 + (tsel & 1) * 8 + rin;
                const uint32_t sw = SMEM_SWIZZLE_128B((uint32_t)(row * 128 + col * 2));
                ldsm_x4(sAh + sw, ah[mi][0], ah[mi][1], ah[mi][2], ah[mi][3]);
                ldsm_x4(sAl + sw, al[mi][0], al[mi][1], al[mi][2], al[mi][3]);
            }
            uint32_t bh[4][2], bl[4][2];
            #pragma unroll
            for (int g = 0; g < 2; g++) {
                const int row = wn + g * 16 + (tsel & 1) * 8 + rin;
                const uint32_t sw = SMEM_SWIZZLE_128B((uint32_t)(row * 128 + col * 2));
                uint32_t r0, r1, r2, r3;
                ldsm_x4(sBh + sw, r0, r1, r2, r3);
                bh[g * 2 + 0][0] = r0; bh[g * 2 + 0][1] = r2;
                bh[g * 2 + 1][0] = r1; bh[g * 2 + 1][1] = r3;
                ldsm_x4(sBl + sw, r0, r1, r2, r3);
                bl[g * 2 + 0][0] = r0; bl[g * 2 + 0][1] = r2;
                bl[g * 2 + 1][0] = r1; bl[g * 2 + 1][1] = r3;
            }
            #pragma unroll
            for (int mi = 0; mi < 4; mi++)
                #pragma unroll
                for (int nj = 0; nj < 4; nj++) {
                    mma_bf16(acc[mi][nj], ah[mi], bh[nj]);
                    mma_bf16(acc[mi][nj], ah[mi], bl[nj]);
                    mma_bf16(acc[mi][nj], al[mi], bh[nj]);
                }
        }
        __syncthreads();
    }

    // ---------------- fused LSTM cell epilogue ----------------
    // gate-interleaved columns: col j' = hh*4 + gate. Thread q even holds (i,f);
    // partner (q^1) holds (g,o). shfl pairs them; even lane computes.
    const int r0 = lane >> 2;
    const int q  = lane & 3;
    #pragma unroll
    for (int mi = 0; mi < 4; mi++) {
        const int m0 = blockIdx.y * 128 + wm + mi * 16 + r0;
        const int m1 = m0 + 8;
        #pragma unroll
        for (int nj = 0; nj < 4; nj++) {
            float v0 = acc[mi][nj][0], v1 = acc[mi][nj][1];
            float v2 = acc[mi][nj][2], v3 = acc[mi][nj][3];
            float p0 = __shfl_xor_sync(0xFFFFFFFFu, v0, 1);
            float p1 = __shfl_xor_sync(0xFFFFFFFFu, v1, 1);
            float p2 = __shfl_xor_sync(0xFFFFFFFFu, v2, 1);
            float p3 = __shfl_xor_sync(0xFFFFFFFFu, v3, 1);
            if ((q & 1) == 0) {
                const int jb = blockIdx.x * 128 + wn + nj * 8;
                const int hh = (jb >> 2) + (q >> 1);
                #pragma unroll
                for (int rr = 0; rr < 2; rr++) {
                    const int m = rr ? m1 : m0;
                    const float gi_ = (rr ? v2 : v0);
                    const float gf_ = (rr ? v3 : v1);
                    const float gg_ = (rr ? p2 : p0);
                    const float go_ = (rr ? p3 : p1);
                    const float4 gxv = *(const float4*)(gx + (size_t)m * GG + hh * 4);
                    const float gi = gi_ + gxv.x;
                    const float gf = gf_ + gxv.y;
                    const float gg = gg_ + gxv.z;
                    const float go = go_ + gxv.w;
                    const size_t ci = (size_t)m * HH + hh;
                    const float i = 1.f / (1.f + expf(-gi));
                    const float f = 1.f / (1.f + expf(-gf));
                    const float g = tanhf(gg);
                    const float o = 1.f / (1.f + expf(-go));
                    const float cn = f * c_state[ci] + i * g;
                    const float hn = o * tanhf(cn);
                    c_state[ci] = cn;
                    const bf16 hb = __float2bfloat16(hn);
                    hhi[ci] = hb;
                    hlo[ci] = __float2bfloat16(hn - __bfloat162float(hb));
                    out_t[ci] = hn;
                }
            }
        }
    }
}

__global__ void copy_hc_kernel(const float* __restrict__ last_h, float* __restrict__ dst) {
    int i = blockIdx.x * blockDim.x + threadIdx.x;
    if (i < BH) { dst[i] = last_h[i]; dst[BH + i] = g_c[i]; }
}

// ---------------- launch ----------------
extern "C" void kernel_launch(void* const* d_in, const int* in_sizes, int n_in,
                              void* d_out, int out_size) {
    const float* inputs = (const float*)d_in[0];
    const float* h0     = (const float*)d_in[1];
    const float* c0     = (const float*)d_in[2];
    const float* W_emb  = (const float*)d_in[3];
    const float* b_emb  = (const float*)d_in[4];
    const float* W_ih   = (const float*)d_in[5];
    const float* W_hh   = (const float*)d_in[6];
    const float* b_ih   = (const float*)d_in[7];
    const float* b_hh   = (const float*)d_in[8];
    float* out = (float*)d_out;

    float *p_xr, *p_gx, *p_bias, *p_c;
    bf16 *p_ehi, *p_elo, *p_hhi, *p_hlo;
    bf16 *p_wihh, *p_wihl, *p_whhh, *p_whhl;
    cudaGetSymbolAddress((void**)&p_xr,   g_xr);
    cudaGetSymbolAddress((void**)&p_ehi,  g_ehi);
    cudaGetSymbolAddress((void**)&p_elo,  g_elo);
    cudaGetSymbolAddress((void**)&p_gx,   g_gx);
    cudaGetSymbolAddress((void**)&p_c,    g_c);
    cudaGetSymbolAddress((void**)&p_hhi,  g_hhi);
    cudaGetSymbolAddress((void**)&p_hlo,  g_hlo);
    cudaGetSymbolAddress((void**)&p_bias, g_bias);
    cudaGetSymbolAddress((void**)&p_wihh, g_wih_hi);
    cudaGetSymbolAddress((void**)&p_wihl, g_wih_lo);
    cudaGetSymbolAddress((void**)&p_whhh, g_whh_hi);
    cudaGetSymbolAddress((void**)&p_whhl, g_whh_lo);

    cudaFuncSetAttribute(mma_gemm_3p,
                         cudaFuncAttributeMaxDynamicSharedMemorySize, SMEM_3P_BYTES);
    cudaFuncSetAttribute(mma_gemm_cell,
                         cudaFuncAttributeMaxDynamicSharedMemorySize, SMEM_FUSED_BYTES);

    // prep
    reorder_kernel<<<(M1 * INN + 255) / 256, 256>>>(inputs);
    bias_init_kernel<<<(GG + 255) / 256, 256>>>(b_ih, b_hh);
    state_init_kernel<<<(BH + 255) / 256, 256>>>(h0, c0);
    decomp_perm_kernel<<<(GG * HH + 255) / 256, 256>>>(W_ih, p_wihh, p_wihl);
    decomp_perm_kernel<<<(GG * HH + 255) / 256, 256>>>(W_hh, p_whhh, p_whhl);

    // embed (SIMT fp32, K=77): emb = xr @ W_emb^T + b_emb -> bf16 hi/lo
    sgemm_nt_hilo<128, 128, 8, 8, 8><<<dim3(HH / 128, M1 / 128), 256>>>(
        p_xr, W_emb, b_emb, p_ehi, p_elo, M1, HH, INN);

    // gx = emb @ W_ih'^T + bias' (gate-interleaved columns) — R4-proven config
    mma_gemm_3p<<<dim3(GG / 128, M1 / 128), 256, SMEM_3P_BYTES>>>(
        p_ehi, p_elo, p_wihh, p_wihl, p_bias, p_gx, HH, GG);

    // recurrence: one fused GEMM+cell launch per step
    for (int t = 0; t < AA; t++) {
        mma_gemm_cell<<<dim3(GG / 128, BB / 128), 256, SMEM_FUSED_BYTES>>>(
            p_hhi, p_hlo, p_whhh, p_whhl,
            p_gx + (size_t)t * BB * GG, p_c, p_hhi, p_hlo, out + (size_t)t * BH);
    }

    // final (h, c) after output — only if the harness buffer includes them
    if (out_size >= (AA + 2) * BH) {
        copy_hc_kernel<<<(BH + 255) / 256, 256>>>(out + (size_t)(AA - 1) * BH,
                                                  out + (size_t)AA * BH);
    }
}

// round 7
// speedup vs baseline: 1.1453x; 1.1453x over previous
#include <cuda_runtime.h>
#include <cuda_bf16.h>
#include <cstdint>
#include <cstddef>

// Problem constants
#define BB   512
#define AA   100
#define HH   1024
#define INN  77          // S*T = 7*11
#define KPAD 128         // embedding K padded to 128
#define GG   4096        // 4*H
#define M1   (AA*BB)     // 51200
#define BH   (BB*HH)     // 524288

typedef __nv_bfloat16 bf16;

// ---------------- scratch (device globals; no allocation allowed) ----------------
__device__ bf16  g_xhi   [(size_t)M1 * KPAD];  // reordered+padded inputs hi
__device__ bf16  g_xlo   [(size_t)M1 * KPAD];  // reordered+padded inputs lo
__device__ bf16  g_wemb_hi[(size_t)HH * KPAD]; // W_emb padded hi
__device__ bf16  g_wemb_lo[(size_t)HH * KPAD];
__device__ bf16  g_ehi   [(size_t)M1 * HH];    // embedded hi (bf16)
__device__ bf16  g_elo   [(size_t)M1 * HH];    // embedded lo (bf16)
__device__ float g_gx    [(size_t)M1 * GG];    // precomputed input gates [A*B, 4H]
__device__ float g_gh    [(size_t)BB * GG];    // recurrent gates, current step
__device__ bf16  g_hhi   [BH];
__device__ bf16  g_hlo   [BH];
__device__ float g_c     [BH];
__device__ float g_bias  [GG];
__device__ bf16  g_wih_hi[(size_t)GG * HH];
__device__ bf16  g_wih_lo[(size_t)GG * HH];
__device__ bf16  g_whh_hi[(size_t)GG * HH];
__device__ bf16  g_whh_lo[(size_t)GG * HH];

// ================= PTX helpers (sm_80+ standard; NO arch-'a' features) =========
__device__ __forceinline__ uint32_t smem_u32(const void* p) {
    uint32_t a;
    asm("{ .reg .u64 t; cvta.to.shared.u64 t, %1; cvt.u32.u64 %0, t; }" : "=r"(a) : "l"(p));
    return a;
}
#define SMEM_SWIZZLE_128B(o) ((o) ^ (((o) >> 3) & 0x70))

__device__ __forceinline__ void cp_async16(uint32_t smem_addr, const void* gptr) {
    asm volatile("cp.async.cg.shared.global [%0], [%1], 16;"
                 :: "r"(smem_addr), "l"(gptr) : "memory");
}
#define CP_COMMIT() asm volatile("cp.async.commit_group;" ::: "memory")
#define CP_WAIT(n)  asm volatile("cp.async.wait_group %0;" :: "n"(n) : "memory")

__device__ __forceinline__ void ldsm_x4(uint32_t addr, uint32_t& r0, uint32_t& r1,
                                        uint32_t& r2, uint32_t& r3) {
    asm volatile("ldmatrix.sync.aligned.m8n8.x4.shared.b16 {%0,%1,%2,%3}, [%4];"
                 : "=r"(r0), "=r"(r1), "=r"(r2), "=r"(r3) : "r"(addr));
}

__device__ __forceinline__ void mma_bf16(float* d, const uint32_t* a, const uint32_t* b) {
    asm volatile(
        "mma.sync.aligned.m16n8k16.row.col.f32.bf16.bf16.f32 "
        "{%0,%1,%2,%3}, {%4,%5,%6,%7}, {%8,%9}, {%0,%1,%2,%3};"
        : "+f"(d[0]), "+f"(d[1]), "+f"(d[2]), "+f"(d[3])
        : "r"(a[0]), "r"(a[1]), "r"(a[2]), "r"(a[3]), "r"(b[0]), "r"(b[1]));
}

// ================= prep kernels =================
// inputs[b, a*S+s, t] -> padded bf16 hi/lo xr[(a*B+b), 0..127]
__global__ void reorder_pad_kernel(const float* __restrict__ inputs) {
    int idx = blockIdx.x * blockDim.x + threadIdx.x;
    if (idx >= M1 * KPAD) return;
    int i = idx & (KPAD - 1);
    int r = idx >> 7;         // r = a*B + b
    int b = r % BB;
    int a = r / BB;
    float v = (i < INN) ? inputs[(size_t)b * (AA * INN) + (size_t)a * INN + i] : 0.f;
    bf16 hb = __float2bfloat16(v);
    g_xhi[idx] = hb;
    g_xlo[idx] = __float2bfloat16(v - __bfloat162float(hb));
}

// W_emb [H,77] -> padded bf16 hi/lo [H,128]
__global__ void decomp_wemb_kernel(const float* __restrict__ W_emb) {
    int idx = blockIdx.x * blockDim.x + threadIdx.x;
    if (idx >= HH * KPAD) return;
    int k = idx & (KPAD - 1);
    int h = idx >> 7;
    float v = (k < INN) ? W_emb[(size_t)h * INN + k] : 0.f;
    bf16 hb = __float2bfloat16(v);
    g_wemb_hi[idx] = hb;
    g_wemb_lo[idx] = __float2bfloat16(v - __bfloat162float(hb));
}

__global__ void bias_init_kernel(const float* __restrict__ b_ih, const float* __restrict__ b_hh) {
    int j = blockIdx.x * blockDim.x + threadIdx.x;
    if (j < GG) g_bias[j] = b_ih[j] + b_hh[j];
}

__global__ void state_init_kernel(const float* __restrict__ h0, const float* __restrict__ c0) {
    int i = blockIdx.x * blockDim.x + threadIdx.x;
    if (i >= BH) return;
    float h = h0[i];
    bf16 hb = __float2bfloat16(h);
    g_hhi[i] = hb;
    g_hlo[i] = __float2bfloat16(h - __bfloat162float(hb));
    g_c[i] = c0[i];
}

__global__ void decomp_bf16_kernel(const float* __restrict__ src, bf16* __restrict__ hi,
                                   bf16* __restrict__ lo, int n) {
    int i = blockIdx.x * blockDim.x + threadIdx.x;
    if (i >= n) return;
    float v = src[i];
    bf16 hb = __float2bfloat16(v);
    hi[i] = hb;
    lo[i] = __float2bfloat16(v - __bfloat162float(hb));
}

// ================= R4-proven 3-pass bf16-split GEMM (256 thr, 2 CTAs/SM) =========
// C[M,N] = A*B^T where A = Ahi+Alo, B = Bhi+Blo (bf16 pairs), fp32 accum.
// 3 passes over K: (Ahi,Bhi), (Ahi,Blo), (Alo,Bhi). AlBl dropped (~2^-18).
// CTA tile 128x128, 8 warps (2x4), warp tile 64x32, K-chunk 64, cp.async 2-stage.
// EPI_HILO: write bf16 hi/lo result (for the embedding); else float C.
#define CHUNK3P 64
#define OPT3P_BYTES 16384               // 128 rows * 128 bytes
#define STAGE3P_BYTES (2 * OPT3P_BYTES)
#define SMEM_3P_BYTES (2 * STAGE3P_BYTES + 1024)

template<bool EPI_HILO>
__global__ __launch_bounds__(256, 2)
void mma_gemm_3p(const bf16* __restrict__ Ahi, const bf16* __restrict__ Alo,
                 const bf16* __restrict__ Bhi, const bf16* __restrict__ Blo,
                 const float* __restrict__ bias, float* __restrict__ C,
                 bf16* __restrict__ Chi, bf16* __restrict__ Clo,
                 int K, int ldc) {
    extern __shared__ char sm[];
    const uint32_t base = (smem_u32(sm) + 1023u) & ~1023u;
    const int tid = threadIdx.x;
    const int wid = tid >> 5, lane = tid & 31;
    const int wm = (wid >> 2) * 64;
    const int wn = (wid & 3) * 32;

    const int cpp = K / CHUNK3P;
    const int total = 3 * cpp;

    const bf16* Aps[3] = {Ahi, Ahi, Alo};
    const bf16* Bps[3] = {Bhi, Blo, Bhi};

    float acc[4][4][4];
    #pragma unroll
    for (int mi = 0; mi < 4; mi++)
        #pragma unroll
        for (int nj = 0; nj < 4; nj++)
            #pragma unroll
            for (int q = 0; q < 4; q++) acc[mi][nj][q] = 0.f;

    auto prefetch = [&](int ch) {
        const int p = ch / cpp;
        const int kc = (ch % cpp) * CHUNK3P;
        const bf16* Ab = Aps[p] + (size_t)blockIdx.y * 128 * K + kc;
        const bf16* Bb = Bps[p] + (size_t)blockIdx.x * 128 * K + kc;
        const uint32_t sA = base + (uint32_t)(ch & 1) * STAGE3P_BYTES;
        const uint32_t sB = sA + OPT3P_BYTES;
        #pragma unroll
        for (int it = 0; it < 4; it++) {
            const int idx = it * 256 + tid;       // 0..1023
            const int row = idx >> 3;
            const int c8  = idx & 7;
            const uint32_t off = SMEM_SWIZZLE_128B((uint32_t)(row * 128 + c8 * 16));
            cp_async16(sA + off, Ab + (size_t)row * K + c8 * 8);
            cp_async16(sB + off, Bb + (size_t)row * K + c8 * 8);
        }
    };

    prefetch(0);
    CP_COMMIT();

    const int tsel = lane >> 3, rin = lane & 7;

    for (int ch = 0; ch < total; ch++) {
        if (ch + 1 < total) {
            prefetch(ch + 1);
            CP_COMMIT();
            CP_WAIT(1);
        } else {
            CP_WAIT(0);
        }
        __syncthreads();

        const uint32_t sA = base + (uint32_t)(ch & 1) * STAGE3P_BYTES;
        const uint32_t sB = sA + OPT3P_BYTES;

        #pragma unroll
        for (int kk = 0; kk < CHUNK3P; kk += 16) {
            const int col = kk + (tsel >> 1) * 8;
            uint32_t a[4][4];
            #pragma unroll
            for (int mi = 0; mi < 4; mi++) {
                const int row = wm + mi * 16 + (tsel & 1) * 8 + rin;
                const uint32_t addr = sA + SMEM_SWIZZLE_128B((uint32_t)(row * 128 + col * 2));
                ldsm_x4(addr, a[mi][0], a[mi][1], a[mi][2], a[mi][3]);
            }
            uint32_t b[4][2];
            #pragma unroll
            for (int g = 0; g < 2; g++) {
                const int row = wn + g * 16 + (tsel & 1) * 8 + rin;
                const uint32_t addr = sB + SMEM_SWIZZLE_128B((uint32_t)(row * 128 + col * 2));
                uint32_t r0, r1, r2, r3;
                ldsm_x4(addr, r0, r1, r2, r3);
                b[g * 2 + 0][0] = r0; b[g * 2 + 0][1] = r2;
                b[g * 2 + 1][0] = r1; b[g * 2 + 1][1] = r3;
            }
            #pragma unroll
            for (int mi = 0; mi < 4; mi++)
                #pragma unroll
                for (int nj = 0; nj < 4; nj++)
                    mma_bf16(acc[mi][nj], a[mi], b[nj]);
        }
        __syncthreads();
    }

    // epilogue
    const int r0 = lane >> 2;
    const int c0 = (lane & 3) * 2;
    #pragma unroll
    for (int mi = 0; mi < 4; mi++) {
        const size_t m0 = (size_t)blockIdx.y * 128 + wm + mi * 16;
        #pragma unroll
        for (int nj = 0; nj < 4; nj++) {
            const int n = blockIdx.x * 128 + wn + nj * 8 + c0;
            float bx = 0.f, by = 0.f;
            if (bias) { bx = bias[n]; by = bias[n + 1]; }
            float vs[4] = {acc[mi][nj][0] + bx, acc[mi][nj][1] + by,
                           acc[mi][nj][2] + bx, acc[mi][nj][3] + by};
            if (!EPI_HILO) {
                *(float2*)(C + (m0 + r0) * (size_t)ldc + n) = make_float2(vs[0], vs[1]);
                *(float2*)(C + (m0 + r0 + 8) * (size_t)ldc + n) = make_float2(vs[2], vs[3]);
            } else {
                #pragma unroll
                for (int rr = 0; rr < 2; rr++) {
                    const size_t mrow = m0 + r0 + rr * 8;
                    const float vx = vs[rr * 2], vy = vs[rr * 2 + 1];
                    const bf16 hx = __float2bfloat16(vx);
                    const bf16 hy = __float2bfloat16(vy);
                    Chi[mrow * (size_t)ldc + n]     = hx;
                    Chi[mrow * (size_t)ldc + n + 1] = hy;
                    Clo[mrow * (size_t)ldc + n]     = __float2bfloat16(vx - __bfloat162float(hx));
                    Clo[mrow * (size_t)ldc + n + 1] = __float2bfloat16(vy - __bfloat162float(hy));
                }
            }
        }
    }
}

// ===== recurrence GEMM: same inner loop, M-tile 64, 128 thr, 3 CTAs/SM =====
// grid (GG/128, BB/64) = (32, 8) = 256 CTAs -> all resident, 2/SM overlap.
#define A64_BYTES 8192                  // 64 rows * 128 bytes
#define B64_BYTES 16384                 // 128 rows * 128 bytes
#define STAGE64_BYTES (A64_BYTES + B64_BYTES)
#define SMEM_M64_BYTES (2 * STAGE64_BYTES + 1024)

__global__ __launch_bounds__(128, 3)
void mma_gemm_3p_m64(const bf16* __restrict__ Ahi, const bf16* __restrict__ Alo,
                     const bf16* __restrict__ Bhi, const bf16* __restrict__ Blo,
                     float* __restrict__ C, int K, int ldc) {
    extern __shared__ char sm[];
    const uint32_t base = (smem_u32(sm) + 1023u) & ~1023u;
    const int tid = threadIdx.x;
    const int wid = tid >> 5, lane = tid & 31;
    const int wn = wid * 32;            // 4 warps across N; all share M=64

    const int cpp = K / CHUNK3P;
    const int total = 3 * cpp;

    const bf16* Aps[3] = {Ahi, Ahi, Alo};
    const bf16* Bps[3] = {Bhi, Blo, Bhi};

    float acc[4][4][4];
    #pragma unroll
    for (int mi = 0; mi < 4; mi++)
        #pragma unroll
        for (int nj = 0; nj < 4; nj++)
            #pragma unroll
            for (int q = 0; q < 4; q++) acc[mi][nj][q] = 0.f;

    auto prefetch = [&](int ch) {
        const int p = ch / cpp;
        const int kc = (ch % cpp) * CHUNK3P;
        const bf16* Ab = Aps[p] + (size_t)blockIdx.y * 64 * K + kc;
        const bf16* Bb = Bps[p] + (size_t)blockIdx.x * 128 * K + kc;
        const uint32_t sA = base + (uint32_t)(ch & 1) * STAGE64_BYTES;
        const uint32_t sB = sA + A64_BYTES;
        #pragma unroll
        for (int it = 0; it < 4; it++) {          // A: 512 x 16B
            const int idx = it * 128 + tid;
            const int row = idx >> 3;
            const int c8  = idx & 7;
            const uint32_t off = SMEM_SWIZZLE_128B((uint32_t)(row * 128 + c8 * 16));
            cp_async16(sA + off, Ab + (size_t)row * K + c8 * 8);
        }
        #pragma unroll
        for (int it = 0; it < 8; it++) {          // B: 1024 x 16B
            const int idx = it * 128 + tid;
            const int row = idx >> 3;
            const int c8  = idx & 7;
            const uint32_t off = SMEM_SWIZZLE_128B((uint32_t)(row * 128 + c8 * 16));
            cp_async16(sB + off, Bb + (size_t)row * K + c8 * 8);
        }
    };

    prefetch(0);
    CP_COMMIT();

    const int tsel = lane >> 3, rin = lane & 7;

    for (int ch = 0; ch < total; ch++) {
        if (ch + 1 < total) {
            prefetch(ch + 1);
            CP_COMMIT();
            CP_WAIT(1);
        } else {
            CP_WAIT(0);
        }
        __syncthreads();

        const uint32_t sA = base + (uint32_t)(ch & 1) * STAGE64_BYTES;
        const uint32_t sB = sA + A64_BYTES;

        #pragma unroll
        for (int kk = 0; kk < CHUNK3P; kk += 16) {
            const int col = kk + (tsel >> 1) * 8;
            uint32_t a[4][4];
            #pragma unroll
            for (int mi = 0; mi < 4; mi++) {
                const int row = mi * 16 + (tsel & 1) * 8 + rin;
                const uint32_t addr = sA + SMEM_SWIZZLE_128B((uint32_t)(row * 128 + col * 2));
                ldsm_x4(addr, a[mi][0], a[mi][1], a[mi][2], a[mi][3]);
            }
            uint32_t b[4][2];
            #pragma unroll
            for (int g = 0; g < 2; g++) {
                const int row = wn + g * 16 + (tsel & 1) * 8 + rin;
                const uint32_t addr = sB + SMEM_SWIZZLE_128B((uint32_t)(row * 128 + col * 2));
                uint32_t r0, r1, r2, r3;
                ldsm_x4(addr, r0, r1, r2, r3);
                b[g * 2 + 0][0] = r0; b[g * 2 + 0][1] = r2;
                b[g * 2 + 1][0] = r1; b[g * 2 + 1][1] = r3;
            }
            #pragma unroll
            for (int mi = 0; mi < 4; mi++)
                #pragma unroll
                for (int nj = 0; nj < 4; nj++)
                    mma_bf16(acc[mi][nj], a[mi], b[nj]);
        }
        __syncthreads();
    }

    // epilogue (no bias)
    const int r0 = lane >> 2;
    const int c0 = (lane & 3) * 2;
    #pragma unroll
    for (int mi = 0; mi < 4; mi++) {
        const size_t m0 = (size_t)blockIdx.y * 64 + mi * 16;
        #pragma unroll
        for (int nj = 0; nj < 4; nj++) {
            const int n = blockIdx.x * 128 + wn + nj * 8 + c0;
            *(float2*)(C + (m0 + r0) * (size_t)ldc + n) =
                make_float2(acc[mi][nj][0], acc[mi][nj][1]);
            *(float2*)(C + (m0 + r0 + 8) * (size_t)ldc + n) =
                make_float2(acc[mi][nj][2], acc[mi][nj][3]);
        }
    }
}

// ---------------- LSTM cell elementwise (R4-proven) ----------------
__global__ void lstm_cell_kernel(const float* __restrict__ gx, float* __restrict__ out_t) {
    int idx = blockIdx.x * blockDim.x + threadIdx.x;
    if (idx >= BH) return;
    int b = idx / HH, hh = idx % HH;
    size_t base = (size_t)b * GG;
    float gi = gx[base + hh]          + g_gh[base + hh];
    float gf = gx[base + HH + hh]     + g_gh[base + HH + hh];
    float gg = gx[base + 2 * HH + hh] + g_gh[base + 2 * HH + hh];
    float go = gx[base + 3 * HH + hh] + g_gh[base + 3 * HH + hh];
    float i = 1.f / (1.f + expf(-gi));
    float f = 1.f / (1.f + expf(-gf));
    float g = tanhf(gg);
    float o = 1.f / (1.f + expf(-go));
    float cn = f * g_c[idx] + i * g;
    float hn = o * tanhf(cn);
    g_c[idx] = cn;
    bf16 hb = __float2bfloat16(hn);
    g_hhi[idx] = hb;
    g_hlo[idx] = __float2bfloat16(hn - __bfloat162float(hb));
    out_t[idx] = hn;
}

__global__ void copy_hc_kernel(const float* __restrict__ last_h, float* __restrict__ dst) {
    int i = blockIdx.x * blockDim.x + threadIdx.x;
    if (i < BH) { dst[i] = last_h[i]; dst[BH + i] = g_c[i]; }
}

// ---------------- launch ----------------
extern "C" void kernel_launch(void* const* d_in, const int* in_sizes, int n_in,
                              void* d_out, int out_size) {
    const float* inputs = (const float*)d_in[0];
    const float* h0     = (const float*)d_in[1];
    const float* c0     = (const float*)d_in[2];
    const float* W_emb  = (const float*)d_in[3];
    const float* b_emb  = (const float*)d_in[4];
    const float* W_ih   = (const float*)d_in[5];
    const float* W_hh   = (const float*)d_in[6];
    const float* b_ih   = (const float*)d_in[7];
    const float* b_hh   = (const float*)d_in[8];
    float* out = (float*)d_out;

    // Real device addresses of scratch globals (host-shadow trap otherwise).
    float *p_gx, *p_gh, *p_bias;
    bf16 *p_xhi, *p_xlo, *p_wembh, *p_wembl, *p_ehi, *p_elo, *p_hhi, *p_hlo;
    bf16 *p_wihh, *p_wihl, *p_whhh, *p_whhl;
    cudaGetSymbolAddress((void**)&p_xhi,  g_xhi);
    cudaGetSymbolAddress((void**)&p_xlo,  g_xlo);
    cudaGetSymbolAddress((void**)&p_wembh,g_wemb_hi);
    cudaGetSymbolAddress((void**)&p_wembl,g_wemb_lo);
    cudaGetSymbolAddress((void**)&p_ehi,  g_ehi);
    cudaGetSymbolAddress((void**)&p_elo,  g_elo);
    cudaGetSymbolAddress((void**)&p_gx,   g_gx);
    cudaGetSymbolAddress((void**)&p_gh,   g_gh);
    cudaGetSymbolAddress((void**)&p_hhi,  g_hhi);
    cudaGetSymbolAddress((void**)&p_hlo,  g_hlo);
    cudaGetSymbolAddress((void**)&p_bias, g_bias);
    cudaGetSymbolAddress((void**)&p_wihh, g_wih_hi);
    cudaGetSymbolAddress((void**)&p_wihl, g_wih_lo);
    cudaGetSymbolAddress((void**)&p_whhh, g_whh_hi);
    cudaGetSymbolAddress((void**)&p_whhl, g_whh_lo);

    cudaFuncSetAttribute(mma_gemm_3p<false>,
                         cudaFuncAttributeMaxDynamicSharedMemorySize, SMEM_3P_BYTES);
    cudaFuncSetAttribute(mma_gemm_3p<true>,
                         cudaFuncAttributeMaxDynamicSharedMemorySize, SMEM_3P_BYTES);
    cudaFuncSetAttribute(mma_gemm_3p_m64,
                         cudaFuncAttributeMaxDynamicSharedMemorySize, SMEM_M64_BYTES);

    // prep
    reorder_pad_kernel<<<(M1 * KPAD + 255) / 256, 256>>>(inputs);
    decomp_wemb_kernel<<<(HH * KPAD + 255) / 256, 256>>>(W_emb);
    bias_init_kernel<<<(GG + 255) / 256, 256>>>(b_ih, b_hh);
    state_init_kernel<<<(BH + 255) / 256, 256>>>(h0, c0);
    decomp_bf16_kernel<<<(GG * HH + 255) / 256, 256>>>(W_ih, p_wihh, p_wihl, GG * HH);
    decomp_bf16_kernel<<<(GG * HH + 255) / 256, 256>>>(W_hh, p_whhh, p_whhl, GG * HH);

    // embed (tensor cores, padded K=128): emb = x @ W_emb^T + b_emb -> bf16 hi/lo
    mma_gemm_3p<true><<<dim3(HH / 128, M1 / 128), 256, SMEM_3P_BYTES>>>(
        p_xhi, p_xlo, p_wembh, p_wembl, b_emb, nullptr, p_ehi, p_elo, KPAD, HH);

    // gx = emb @ W_ih^T + bias  (R4-proven config)
    mma_gemm_3p<false><<<dim3(GG / 128, M1 / 128), 256, SMEM_3P_BYTES>>>(
        p_ehi, p_elo, p_wihh, p_wihl, p_bias, p_gx, nullptr, nullptr, HH, GG);

    // recurrence: M64-tiled GEMM (256 CTAs, all resident) + separate cell
    for (int t = 0; t < AA; t++) {
        mma_gemm_3p_m64<<<dim3(GG / 128, BB / 64), 128, SMEM_M64_BYTES>>>(
            p_hhi, p_hlo, p_whhh, p_whhl, p_gh, HH, GG);
        lstm_cell_kernel<<<(BH + 255) / 256, 256>>>(
            p_gx + (size_t)t * BB * GG, out + (size_t)t * BH);
    }

    // final (h, c) after output — only if the harness buffer includes them
    if (out_size >= (AA + 2) * BH) {
        copy_hc_kernel<<<(BH + 255) / 256, 256>>>(out + (size_t)(AA - 1) * BH,
                                                  out + (size_t)AA * BH);
    }
}

// round 8
// speedup vs baseline: 1.2022x; 1.0497x over previous
#include <cuda_runtime.h>
#include <cuda_bf16.h>
#include <cstdint>
#include <cstddef>

// Problem constants
#define BB   512
#define AA   100
#define HH   1024
#define INN  77          // S*T = 7*11
#define KPAD 128         // embedding K padded to 128
#define GG   4096        // 4*H
#define M1   (AA*BB)     // 51200
#define BH   (BB*HH)     // 524288

typedef __nv_bfloat16 bf16;

// ---------------- scratch (device globals; no allocation allowed) ----------------
__device__ bf16  g_xhi   [(size_t)M1 * KPAD];
__device__ bf16  g_xlo   [(size_t)M1 * KPAD];
__device__ bf16  g_wemb_hi[(size_t)HH * KPAD];
__device__ bf16  g_wemb_lo[(size_t)HH * KPAD];
__device__ bf16  g_ehi   [(size_t)M1 * HH];
__device__ bf16  g_elo   [(size_t)M1 * HH];
__device__ float g_gx    [(size_t)M1 * GG];
__device__ float g_gh    [(size_t)BB * GG];
__device__ bf16  g_hhi   [BH];
__device__ bf16  g_hlo   [BH];
__device__ float g_c     [BH];
__device__ float g_bias  [GG];
__device__ bf16  g_wih_hi[(size_t)GG * HH];
__device__ bf16  g_wih_lo[(size_t)GG * HH];
__device__ bf16  g_whh_hi[(size_t)GG * HH];
__device__ bf16  g_whh_lo[(size_t)GG * HH];

// ================= PTX helpers (sm_80+ standard; NO arch-'a' features) =========
__device__ __forceinline__ uint32_t smem_u32(const void* p) {
    uint32_t a;
    asm("{ .reg .u64 t; cvta.to.shared.u64 t, %1; cvt.u32.u64 %0, t; }" : "=r"(a) : "l"(p));
    return a;
}
#define SMEM_SWIZZLE_128B(o) ((o) ^ (((o) >> 3) & 0x70))

__device__ __forceinline__ void cp_async16(uint32_t smem_addr, const void* gptr) {
    asm volatile("cp.async.cg.shared.global [%0], [%1], 16;"
                 :: "r"(smem_addr), "l"(gptr) : "memory");
}
#define CP_COMMIT() asm volatile("cp.async.commit_group;" ::: "memory")
#define CP_WAIT(n)  asm volatile("cp.async.wait_group %0;" :: "n"(n) : "memory")

__device__ __forceinline__ void ldsm_x4(uint32_t addr, uint32_t& r0, uint32_t& r1,
                                        uint32_t& r2, uint32_t& r3) {
    asm volatile("ldmatrix.sync.aligned.m8n8.x4.shared.b16 {%0,%1,%2,%3}, [%4];"
                 : "=r"(r0), "=r"(r1), "=r"(r2), "=r"(r3) : "r"(addr));
}

__device__ __forceinline__ void mma_bf16(float* d, const uint32_t* a, const uint32_t* b) {
    asm volatile(
        "mma.sync.aligned.m16n8k16.row.col.f32.bf16.bf16.f32 "
        "{%0,%1,%2,%3}, {%4,%5,%6,%7}, {%8,%9}, {%0,%1,%2,%3};"
        : "+f"(d[0]), "+f"(d[1]), "+f"(d[2]), "+f"(d[3])
        : "r"(a[0]), "r"(a[1]), "r"(a[2]), "r"(a[3]), "r"(b[0]), "r"(b[1]));
}

// ================= prep kernels =================
__global__ void reorder_pad_kernel(const float* __restrict__ inputs) {
    int idx = blockIdx.x * blockDim.x + threadIdx.x;
    if (idx >= M1 * KPAD) return;
    int i = idx & (KPAD - 1);
    int r = idx >> 7;         // r = a*B + b
    int b = r % BB;
    int a = r / BB;
    float v = (i < INN) ? inputs[(size_t)b * (AA * INN) + (size_t)a * INN + i] : 0.f;
    bf16 hb = __float2bfloat16(v);
    g_xhi[idx] = hb;
    g_xlo[idx] = __float2bfloat16(v - __bfloat162float(hb));
}

__global__ void decomp_wemb_kernel(const float* __restrict__ W_emb) {
    int idx = blockIdx.x * blockDim.x + threadIdx.x;
    if (idx >= HH * KPAD) return;
    int k = idx & (KPAD - 1);
    int h = idx >> 7;
    float v = (k < INN) ? W_emb[(size_t)h * INN + k] : 0.f;
    bf16 hb = __float2bfloat16(v);
    g_wemb_hi[idx] = hb;
    g_wemb_lo[idx] = __float2bfloat16(v - __bfloat162float(hb));
}

__global__ void bias_init_kernel(const float* __restrict__ b_ih, const float* __restrict__ b_hh) {
    int j = blockIdx.x * blockDim.x + threadIdx.x;
    if (j < GG) g_bias[j] = b_ih[j] + b_hh[j];
}

__global__ void state_init_kernel(const float* __restrict__ h0, const float* __restrict__ c0) {
    int i = blockIdx.x * blockDim.x + threadIdx.x;
    if (i >= BH) return;
    float h = h0[i];
    bf16 hb = __float2bfloat16(h);
    g_hhi[i] = hb;
    g_hlo[i] = __float2bfloat16(h - __bfloat162float(hb));
    g_c[i] = c0[i];
}

__global__ void decomp_bf16_kernel(const float* __restrict__ src, bf16* __restrict__ hi,
                                   bf16* __restrict__ lo, int n) {
    int i = blockIdx.x * blockDim.x + threadIdx.x;
    if (i >= n) return;
    float v = src[i];
    bf16 hb = __float2bfloat16(v);
    hi[i] = hb;
    lo[i] = __float2bfloat16(v - __bfloat162float(hb));
}

// ============== fused single-pass bf16-split GEMM, occupancy-tuned =============
// C[M,N] = (Ahi+Alo) @ (Bhi+Blo)^T (+bias); 3 MMA terms per fragment pair
// (AhBh, AhBl, AlBh; AlBl dropped ~2^-18). CTA tile 64x128, 4 warps (warp tile
// 64x32), K-chunk 32 with hi|lo interleaved per 128B smem row:
//   row m: bytes [0,64) = hi[m, k0:k0+32], bytes [64,128) = lo[m, k0:k0+32]
// so SW128 swizzle stays conflict-free. 3-stage cp.async; 3 CTAs/SM.
// EPI: 0 = float C (+bias), 1 = bf16 hi/lo (+bias).
#define FCHUNK 32
#define A_TILE 8192                     // 64 rows * 128B
#define B_TILE 16384                    // 128 rows * 128B
#define F_STAGE (A_TILE + B_TILE)       // 24 KB
#define F_NSTAGE 3
#define SMEM_F_BYTES (F_NSTAGE * F_STAGE + 1024)

template<int EPI>
__global__ __launch_bounds__(128, 3)
void mma_gemm_f(const bf16* __restrict__ Ahi, const bf16* __restrict__ Alo,
                const bf16* __restrict__ Bhi, const bf16* __restrict__ Blo,
                const float* __restrict__ bias, float* __restrict__ C,
                bf16* __restrict__ Chi, bf16* __restrict__ Clo,
                int K, int ldc) {
    extern __shared__ char sm[];
    const uint32_t base = (smem_u32(sm) + 1023u) & ~1023u;
    const int tid = threadIdx.x;
    const int wid = tid >> 5, lane = tid & 31;
    const int wn = wid * 32;            // 4 warps across N; M=64 shared

    const bf16* Ahi_b = Ahi + (size_t)blockIdx.y * 64 * K;
    const bf16* Alo_b = Alo + (size_t)blockIdx.y * 64 * K;
    const bf16* Bhi_b = Bhi + (size_t)blockIdx.x * 128 * K;
    const bf16* Blo_b = Blo + (size_t)blockIdx.x * 128 * K;

    const int nchunk = K / FCHUNK;

    float acc[4][4][4];
    #pragma unroll
    for (int mi = 0; mi < 4; mi++)
        #pragma unroll
        for (int nj = 0; nj < 4; nj++)
            #pragma unroll
            for (int q = 0; q < 4; q++) acc[mi][nj][q] = 0.f;

    auto prefetch = [&](int ch) {
        const int kc = ch * FCHUNK;
        const uint32_t st = base + (uint32_t)(ch % F_NSTAGE) * F_STAGE;
        // A: 64 rows x 8 x 16B groups; g<4 -> hi(k g*8), g>=4 -> lo((g-4)*8)
        #pragma unroll
        for (int it = 0; it < 4; it++) {
            const int idx = it * 128 + tid;        // 0..511
            const int row = idx >> 3;
            const int g   = idx & 7;
            const uint32_t off = SMEM_SWIZZLE_128B((uint32_t)(row * 128 + g * 16));
            const bf16* src = (g < 4) ? (Ahi_b + (size_t)row * K + kc + g * 8)
                                      : (Alo_b + (size_t)row * K + kc + (g - 4) * 8);
            cp_async16(st + off, src);
        }
        // B: 128 rows x 8 groups
        #pragma unroll
        for (int it = 0; it < 8; it++) {
            const int idx = it * 128 + tid;        // 0..1023
            const int row = idx >> 3;
            const int g   = idx & 7;
            const uint32_t off = SMEM_SWIZZLE_128B((uint32_t)(row * 128 + g * 16));
            const bf16* src = (g < 4) ? (Bhi_b + (size_t)row * K + kc + g * 8)
                                      : (Blo_b + (size_t)row * K + kc + (g - 4) * 8);
            cp_async16(st + A_TILE + off, src);
        }
    };

    prefetch(0); CP_COMMIT();
    prefetch(1); CP_COMMIT();

    const int tsel = lane >> 3, rin = lane & 7;

    for (int ch = 0; ch < nchunk; ch++) {
        if (ch + 2 < nchunk) {
            prefetch(ch + 2);
            CP_COMMIT();
            CP_WAIT(2);
        } else {
            CP_WAIT(0);
        }
        __syncthreads();

        const uint32_t st = base + (uint32_t)(ch % F_NSTAGE) * F_STAGE;
        const uint32_t sB = st + A_TILE;

        #pragma unroll
        for (int kk = 0; kk < FCHUNK; kk += 16) {
            const int colb = (kk + (tsel >> 1) * 8) * 2;   // hi byte col (0..48)
            uint32_t ah[4][4], al[4][4];
            #pragma unroll
            for (int mi = 0; mi < 4; mi++) {
                const int row = mi * 16 + (tsel & 1) * 8 + rin;
                ldsm_x4(st + SMEM_SWIZZLE_128B((uint32_t)(row * 128 + colb)),
                        ah[mi][0], ah[mi][1], ah[mi][2], ah[mi][3]);
                ldsm_x4(st + SMEM_SWIZZLE_128B((uint32_t)(row * 128 + colb + 64)),
                        al[mi][0], al[mi][1], al[mi][2], al[mi][3]);
            }
            uint32_t bh[4][2], bl[4][2];
            #pragma unroll
            for (int g = 0; g < 2; g++) {
                const int row = wn + g * 16 + (tsel & 1) * 8 + rin;
                uint32_t r0, r1, r2, r3;
                ldsm_x4(sB + SMEM_SWIZZLE_128B((uint32_t)(row * 128 + colb)),
                        r0, r1, r2, r3);
                bh[g * 2 + 0][0] = r0; bh[g * 2 + 0][1] = r2;
                bh[g * 2 + 1][0] = r1; bh[g * 2 + 1][1] = r3;
                ldsm_x4(sB + SMEM_SWIZZLE_128B((uint32_t)(row * 128 + colb + 64)),
                        r0, r1, r2, r3);
                bl[g * 2 + 0][0] = r0; bl[g * 2 + 0][1] = r2;
                bl[g * 2 + 1][0] = r1; bl[g * 2 + 1][1] = r3;
            }
            #pragma unroll
            for (int mi = 0; mi < 4; mi++)
                #pragma unroll
                for (int nj = 0; nj < 4; nj++) {
                    mma_bf16(acc[mi][nj], ah[mi], bh[nj]);
                    mma_bf16(acc[mi][nj], ah[mi], bl[nj]);
                    mma_bf16(acc[mi][nj], al[mi], bh[nj]);
                }
        }
        __syncthreads();
    }

    // ---------------- epilogue ----------------
    const int r0 = lane >> 2;
    const int c0 = (lane & 3) * 2;
    #pragma unroll
    for (int mi = 0; mi < 4; mi++) {
        const size_t m0 = (size_t)blockIdx.y * 64 + mi * 16;
        #pragma unroll
        for (int nj = 0; nj < 4; nj++) {
            const int n = blockIdx.x * 128 + wn + nj * 8 + c0;
            float bx = 0.f, by = 0.f;
            if (bias) { bx = bias[n]; by = bias[n + 1]; }
            float vs[4] = {acc[mi][nj][0] + bx, acc[mi][nj][1] + by,
                           acc[mi][nj][2] + bx, acc[mi][nj][3] + by};
            if (EPI == 0) {
                *(float2*)(C + (m0 + r0) * (size_t)ldc + n) = make_float2(vs[0], vs[1]);
                *(float2*)(C + (m0 + r0 + 8) * (size_t)ldc + n) = make_float2(vs[2], vs[3]);
            } else {
                #pragma unroll
                for (int rr = 0; rr < 2; rr++) {
                    const size_t mrow = m0 + r0 + rr * 8;
                    const float vx = vs[rr * 2], vy = vs[rr * 2 + 1];
                    const bf16 hx = __float2bfloat16(vx);
                    const bf16 hy = __float2bfloat16(vy);
                    Chi[mrow * (size_t)ldc + n]     = hx;
                    Chi[mrow * (size_t)ldc + n + 1] = hy;
                    Clo[mrow * (size_t)ldc + n]     = __float2bfloat16(vx - __bfloat162float(hx));
                    Clo[mrow * (size_t)ldc + n + 1] = __float2bfloat16(vy - __bfloat162float(hy));
                }
            }
        }
    }
}

// ---------------- LSTM cell elementwise (proven) ----------------
__global__ void lstm_cell_kernel(const float* __restrict__ gx, float* __restrict__ out_t) {
    int idx = blockIdx.x * blockDim.x + threadIdx.x;
    if (idx >= BH) return;
    int b = idx / HH, hh = idx % HH;
    size_t base = (size_t)b * GG;
    float gi = gx[base + hh]          + g_gh[base + hh];
    float gf = gx[base + HH + hh]     + g_gh[base + HH + hh];
    float gg = gx[base + 2 * HH + hh] + g_gh[base + 2 * HH + hh];
    float go = gx[base + 3 * HH + hh] + g_gh[base + 3 * HH + hh];
    float i = 1.f / (1.f + expf(-gi));
    float f = 1.f / (1.f + expf(-gf));
    float g = tanhf(gg);
    float o = 1.f / (1.f + expf(-go));
    float cn = f * g_c[idx] + i * g;
    float hn = o * tanhf(cn);
    g_c[idx] = cn;
    bf16 hb = __float2bfloat16(hn);
    g_hhi[idx] = hb;
    g_hlo[idx] = __float2bfloat16(hn - __bfloat162float(hb));
    out_t[idx] = hn;
}

__global__ void copy_hc_kernel(const float* __restrict__ last_h, float* __restrict__ dst) {
    int i = blockIdx.x * blockDim.x + threadIdx.x;
    if (i < BH) { dst[i] = last_h[i]; dst[BH + i] = g_c[i]; }
}

// ---------------- launch ----------------
extern "C" void kernel_launch(void* const* d_in, const int* in_sizes, int n_in,
                              void* d_out, int out_size) {
    const float* inputs = (const float*)d_in[0];
    const float* h0     = (const float*)d_in[1];
    const float* c0     = (const float*)d_in[2];
    const float* W_emb  = (const float*)d_in[3];
    const float* b_emb  = (const float*)d_in[4];
    const float* W_ih   = (const float*)d_in[5];
    const float* W_hh   = (const float*)d_in[6];
    const float* b_ih   = (const float*)d_in[7];
    const float* b_hh   = (const float*)d_in[8];
    float* out = (float*)d_out;

    // Real device addresses of scratch globals (host-shadow trap otherwise).
    float *p_gx, *p_gh, *p_bias;
    bf16 *p_xhi, *p_xlo, *p_wembh, *p_wembl, *p_ehi, *p_elo, *p_hhi, *p_hlo;
    bf16 *p_wihh, *p_wihl, *p_whhh, *p_whhl;
    cudaGetSymbolAddress((void**)&p_xhi,  g_xhi);
    cudaGetSymbolAddress((void**)&p_xlo,  g_xlo);
    cudaGetSymbolAddress((void**)&p_wembh,g_wemb_hi);
    cudaGetSymbolAddress((void**)&p_wembl,g_wemb_lo);
    cudaGetSymbolAddress((void**)&p_ehi,  g_ehi);
    cudaGetSymbolAddress((void**)&p_elo,  g_elo);
    cudaGetSymbolAddress((void**)&p_gx,   g_gx);
    cudaGetSymbolAddress((void**)&p_gh,   g_gh);
    cudaGetSymbolAddress((void**)&p_hhi,  g_hhi);
    cudaGetSymbolAddress((void**)&p_hlo,  g_hlo);
    cudaGetSymbolAddress((void**)&p_bias, g_bias);
    cudaGetSymbolAddress((void**)&p_wihh, g_wih_hi);
    cudaGetSymbolAddress((void**)&p_wihl, g_wih_lo);
    cudaGetSymbolAddress((void**)&p_whhh, g_whh_hi);
    cudaGetSymbolAddress((void**)&p_whhl, g_whh_lo);

    cudaFuncSetAttribute(mma_gemm_f<0>,
                         cudaFuncAttributeMaxDynamicSharedMemorySize, SMEM_F_BYTES);
    cudaFuncSetAttribute(mma_gemm_f<1>,
                         cudaFuncAttributeMaxDynamicSharedMemorySize, SMEM_F_BYTES);

    // prep
    reorder_pad_kernel<<<(M1 * KPAD + 255) / 256, 256>>>(inputs);
    decomp_wemb_kernel<<<(HH * KPAD + 255) / 256, 256>>>(W_emb);
    bias_init_kernel<<<(GG + 255) / 256, 256>>>(b_ih, b_hh);
    state_init_kernel<<<(BH + 255) / 256, 256>>>(h0, c0);
    decomp_bf16_kernel<<<(GG * HH + 255) / 256, 256>>>(W_ih, p_wihh, p_wihl, GG * HH);
    decomp_bf16_kernel<<<(GG * HH + 255) / 256, 256>>>(W_hh, p_whhh, p_whhl, GG * HH);

    // embed (tensor cores, padded K=128): emb = x @ W_emb^T + b_emb -> bf16 hi/lo
    mma_gemm_f<1><<<dim3(HH / 128, M1 / 64), 128, SMEM_F_BYTES>>>(
        p_xhi, p_xlo, p_wembh, p_wembl, b_emb, nullptr, p_ehi, p_elo, KPAD, HH);

    // gx = emb @ W_ih^T + bias
    mma_gemm_f<0><<<dim3(GG / 128, M1 / 64), 128, SMEM_F_BYTES>>>(
        p_ehi, p_elo, p_wihh, p_wihl, p_bias, p_gx, nullptr, nullptr, HH, GG);

    // recurrence: fused-load GEMM (256 CTAs, 3/SM) + separate cell
    for (int t = 0; t < AA; t++) {
        mma_gemm_f<0><<<dim3(GG / 128, BB / 64), 128, SMEM_F_BYTES>>>(
            p_hhi, p_hlo, p_whhh, p_whhl, nullptr, p_gh, nullptr, nullptr, HH, GG);
        lstm_cell_kernel<<<(BH + 255) / 256, 256>>>(
            p_gx + (size_t)t * BB * GG, out + (size_t)t * BH);
    }

    // final (h, c) after output — only if the harness buffer includes them
    if (out_size >= (AA + 2) * BH) {
        copy_hc_kernel<<<(BH + 255) / 256, 256>>>(out + (size_t)(AA - 1) * BH,
                                                  out + (size_t)AA * BH);
    }
}

// round 9
// speedup vs baseline: 1.8718x; 1.5570x over previous
#include <cuda_runtime.h>
#include <cuda_bf16.h>
#include <cstdint>
#include <cstddef>

// Problem constants
#define BB   512
#define AA   100
#define HH   1024
#define INN  77          // S*T = 7*11
#define KPAD 128         // padded input-feature dim
#define GG   4096        // 4*H
#define M1   (AA*BB)     // 51200
#define BH   (BB*HH)     // 524288

typedef __nv_bfloat16 bf16;

// ---------------- scratch (device globals; no allocation allowed) ----------------
__device__ bf16  g_xhi    [(size_t)M1 * KPAD];   // reordered+padded inputs hi
__device__ bf16  g_xlo    [(size_t)M1 * KPAD];
__device__ bf16  g_wembT_hi[(size_t)KPAD * HH];  // W_emb^T padded (for Wc GEMM)
__device__ bf16  g_wembT_lo[(size_t)KPAD * HH];
__device__ bf16  g_wc_hi  [(size_t)GG * KPAD];   // Wc = W_ih @ W_emb  [4096,128]
__device__ bf16  g_wc_lo  [(size_t)GG * KPAD];
__device__ float g_bias_c [GG];                  // W_ih@b_emb + b_ih + b_hh
__device__ float g_gx     [(size_t)M1 * GG];     // precomputed input gates
__device__ float g_gh     [(size_t)BB * GG];     // recurrent gates, current step
__device__ bf16  g_hhi    [BH];
__device__ bf16  g_hlo    [BH];
__device__ float g_c      [BH];
__device__ bf16  g_wih_hi [(size_t)GG * HH];
__device__ bf16  g_wih_lo [(size_t)GG * HH];
__device__ bf16  g_whh_hi [(size_t)GG * HH];
__device__ bf16  g_whh_lo [(size_t)GG * HH];

// ================= PTX helpers (sm_80+ standard; NO arch-'a' features) =========
__device__ __forceinline__ uint32_t smem_u32(const void* p) {
    uint32_t a;
    asm("{ .reg .u64 t; cvta.to.shared.u64 t, %1; cvt.u32.u64 %0, t; }" : "=r"(a) : "l"(p));
    return a;
}
#define SMEM_SWIZZLE_128B(o) ((o) ^ (((o) >> 3) & 0x70))

__device__ __forceinline__ void cp_async16(uint32_t smem_addr, const void* gptr) {
    asm volatile("cp.async.cg.shared.global [%0], [%1], 16;"
                 :: "r"(smem_addr), "l"(gptr) : "memory");
}
#define CP_COMMIT() asm volatile("cp.async.commit_group;" ::: "memory")
#define CP_WAIT(n)  asm volatile("cp.async.wait_group %0;" :: "n"(n) : "memory")

__device__ __forceinline__ void ldsm_x4(uint32_t addr, uint32_t& r0, uint32_t& r1,
                                        uint32_t& r2, uint32_t& r3) {
    asm volatile("ldmatrix.sync.aligned.m8n8.x4.shared.b16 {%0,%1,%2,%3}, [%4];"
                 : "=r"(r0), "=r"(r1), "=r"(r2), "=r"(r3) : "r"(addr));
}

__device__ __forceinline__ void mma_bf16(float* d, const uint32_t* a, const uint32_t* b) {
    asm volatile(
        "mma.sync.aligned.m16n8k16.row.col.f32.bf16.bf16.f32 "
        "{%0,%1,%2,%3}, {%4,%5,%6,%7}, {%8,%9}, {%0,%1,%2,%3};"
        : "+f"(d[0]), "+f"(d[1]), "+f"(d[2]), "+f"(d[3])
        : "r"(a[0]), "r"(a[1]), "r"(a[2]), "r"(a[3]), "r"(b[0]), "r"(b[1]));
}

// ================= prep kernels =================
__global__ void reorder_pad_kernel(const float* __restrict__ inputs) {
    int idx = blockIdx.x * blockDim.x + threadIdx.x;
    if (idx >= M1 * KPAD) return;
    int i = idx & (KPAD - 1);
    int r = idx >> 7;         // r = a*B + b
    int b = r % BB;
    int a = r / BB;
    float v = (i < INN) ? inputs[(size_t)b * (AA * INN) + (size_t)a * INN + i] : 0.f;
    bf16 hb = __float2bfloat16(v);
    g_xhi[idx] = hb;
    g_xlo[idx] = __float2bfloat16(v - __bfloat162float(hb));
}

// W_emb [H,77] -> transposed+padded bf16 hi/lo [128, H]
__global__ void transpose_wemb_kernel(const float* __restrict__ W_emb) {
    int idx = blockIdx.x * blockDim.x + threadIdx.x;
    if (idx >= KPAD * HH) return;
    int h = idx & (HH - 1);
    int n = idx >> 10;        // padded input-feature index
    float v = (n < INN) ? W_emb[(size_t)h * INN + n] : 0.f;
    bf16 hb = __float2bfloat16(v);
    g_wembT_hi[idx] = hb;
    g_wembT_lo[idx] = __float2bfloat16(v - __bfloat162float(hb));
}

// bias_c[j] = dot(W_ih[j,:], b_emb) + b_ih[j] + b_hh[j]; one 128-thr block per j
__global__ void bias_c_kernel(const float* __restrict__ W_ih, const float* __restrict__ b_emb,
                              const float* __restrict__ b_ih, const float* __restrict__ b_hh) {
    __shared__ float red[4];
    const int j = blockIdx.x;
    const int tid = threadIdx.x;
    float s = 0.f;
    for (int h = tid; h < HH; h += 128)
        s += W_ih[(size_t)j * HH + h] * b_emb[h];
    #pragma unroll
    for (int o = 16; o > 0; o >>= 1) s += __shfl_down_sync(0xFFFFFFFFu, s, o);
    if ((tid & 31) == 0) red[tid >> 5] = s;
    __syncthreads();
    if (tid == 0)
        g_bias_c[j] = red[0] + red[1] + red[2] + red[3] + b_ih[j] + b_hh[j];
}

__global__ void state_init_kernel(const float* __restrict__ h0, const float* __restrict__ c0) {
    int i = blockIdx.x * blockDim.x + threadIdx.x;
    if (i >= BH) return;
    float h = h0[i];
    bf16 hb = __float2bfloat16(h);
    g_hhi[i] = hb;
    g_hlo[i] = __float2bfloat16(h - __bfloat162float(hb));
    g_c[i] = c0[i];
}

__global__ void decomp_bf16_kernel(const float* __restrict__ src, bf16* __restrict__ hi,
                                   bf16* __restrict__ lo, int n) {
    int i = blockIdx.x * blockDim.x + threadIdx.x;
    if (i >= n) return;
    float v = src[i];
    bf16 hb = __float2bfloat16(v);
    hi[i] = hb;
    lo[i] = __float2bfloat16(v - __bfloat162float(hb));
}

// ============== fused single-pass bf16-split GEMM, occupancy-tuned (R8) ========
// C[M,N] = (Ahi+Alo) @ (Bhi+Blo)^T (+bias); 3 MMA terms (AhBh, AhBl, AlBh).
// CTA tile 64x128, 4 warps (warp tile 64x32), K-chunk 32 with hi|lo interleaved
// per 128B smem row. 3-stage cp.async; 3 CTAs/SM.
// EPI: 0 = float C (+bias), 1 = bf16 hi/lo (+bias).
#define FCHUNK 32
#define A_TILE 8192                     // 64 rows * 128B
#define B_TILE 16384                    // 128 rows * 128B
#define F_STAGE (A_TILE + B_TILE)       // 24 KB
#define F_NSTAGE 3
#define SMEM_F_BYTES (F_NSTAGE * F_STAGE + 1024)

template<int EPI>
__global__ __launch_bounds__(128, 3)
void mma_gemm_f(const bf16* __restrict__ Ahi, const bf16* __restrict__ Alo,
                const bf16* __restrict__ Bhi, const bf16* __restrict__ Blo,
                const float* __restrict__ bias, float* __restrict__ C,
                bf16* __restrict__ Chi, bf16* __restrict__ Clo,
                int K, int ldc) {
    extern __shared__ char sm[];
    const uint32_t base = (smem_u32(sm) + 1023u) & ~1023u;
    const int tid = threadIdx.x;
    const int wid = tid >> 5, lane = tid & 31;
    const int wn = wid * 32;            // 4 warps across N; M=64 shared

    const bf16* Ahi_b = Ahi + (size_t)blockIdx.y * 64 * K;
    const bf16* Alo_b = Alo + (size_t)blockIdx.y * 64 * K;
    const bf16* Bhi_b = Bhi + (size_t)blockIdx.x * 128 * K;
    const bf16* Blo_b = Blo + (size_t)blockIdx.x * 128 * K;

    const int nchunk = K / FCHUNK;

    float acc[4][4][4];
    #pragma unroll
    for (int mi = 0; mi < 4; mi++)
        #pragma unroll
        for (int nj = 0; nj < 4; nj++)
            #pragma unroll
            for (int q = 0; q < 4; q++) acc[mi][nj][q] = 0.f;

    auto prefetch = [&](int ch) {
        const int kc = ch * FCHUNK;
        const uint32_t st = base + (uint32_t)(ch % F_NSTAGE) * F_STAGE;
        #pragma unroll
        for (int it = 0; it < 4; it++) {
            const int idx = it * 128 + tid;        // 0..511
            const int row = idx >> 3;
            const int g   = idx & 7;
            const uint32_t off = SMEM_SWIZZLE_128B((uint32_t)(row * 128 + g * 16));
            const bf16* src = (g < 4) ? (Ahi_b + (size_t)row * K + kc + g * 8)
                                      : (Alo_b + (size_t)row * K + kc + (g - 4) * 8);
            cp_async16(st + off, src);
        }
        #pragma unroll
        for (int it = 0; it < 8; it++) {
            const int idx = it * 128 + tid;        // 0..1023
            const int row = idx >> 3;
            const int g   = idx & 7;
            const uint32_t off = SMEM_SWIZZLE_128B((uint32_t)(row * 128 + g * 16));
            const bf16* src = (g < 4) ? (Bhi_b + (size_t)row * K + kc + g * 8)
                                      : (Blo_b + (size_t)row * K + kc + (g - 4) * 8);
            cp_async16(st + A_TILE + off, src);
        }
    };

    prefetch(0); CP_COMMIT();
    prefetch(1); CP_COMMIT();

    const int tsel = lane >> 3, rin = lane & 7;

    for (int ch = 0; ch < nchunk; ch++) {
        if (ch + 2 < nchunk) {
            prefetch(ch + 2);
            CP_COMMIT();
            CP_WAIT(2);
        } else {
            CP_WAIT(0);
        }
        __syncthreads();

        const uint32_t st = base + (uint32_t)(ch % F_NSTAGE) * F_STAGE;
        const uint32_t sB = st + A_TILE;

        #pragma unroll
        for (int kk = 0; kk < FCHUNK; kk += 16) {
            const int colb = (kk + (tsel >> 1) * 8) * 2;   // hi byte col
            uint32_t ah[4][4], al[4][4];
            #pragma unroll
            for (int mi = 0; mi < 4; mi++) {
                const int row = mi * 16 + (tsel & 1) * 8 + rin;
                ldsm_x4(st + SMEM_SWIZZLE_128B((uint32_t)(row * 128 + colb)),
                        ah[mi][0], ah[mi][1], ah[mi][2], ah[mi][3]);
                ldsm_x4(st + SMEM_SWIZZLE_128B((uint32_t)(row * 128 + colb + 64)),
                        al[mi][0], al[mi][1], al[mi][2], al[mi][3]);
            }
            uint32_t bh[4][2], bl[4][2];
            #pragma unroll
            for (int g = 0; g < 2; g++) {
                const int row = wn + g * 16 + (tsel & 1) * 8 + rin;
                uint32_t r0, r1, r2, r3;
                ldsm_x4(sB + SMEM_SWIZZLE_128B((uint32_t)(row * 128 + colb)),
                        r0, r1, r2, r3);
                bh[g * 2 + 0][0] = r0; bh[g * 2 + 0][1] = r2;
                bh[g * 2 + 1][0] = r1; bh[g * 2 + 1][1] = r3;
                ldsm_x4(sB + SMEM_SWIZZLE_128B((uint32_t)(row * 128 + colb + 64)),
                        r0, r1, r2, r3);
                bl[g * 2 + 0][0] = r0; bl[g * 2 + 0][1] = r2;
                bl[g * 2 + 1][0] = r1; bl[g * 2 + 1][1] = r3;
            }
            #pragma unroll
            for (int mi = 0; mi < 4; mi++)
                #pragma unroll
                for (int nj = 0; nj < 4; nj++) {
                    mma_bf16(acc[mi][nj], ah[mi], bh[nj]);
                    mma_bf16(acc[mi][nj], ah[mi], bl[nj]);
                    mma_bf16(acc[mi][nj], al[mi], bh[nj]);
                }
        }
        __syncthreads();
    }

    // ---------------- epilogue ----------------
    const int r0 = lane >> 2;
    const int c0 = (lane & 3) * 2;
    #pragma unroll
    for (int mi = 0; mi < 4; mi++) {
        const size_t m0 = (size_t)blockIdx.y * 64 + mi * 16;
        #pragma unroll
        for (int nj = 0; nj < 4; nj++) {
            const int n = blockIdx.x * 128 + wn + nj * 8 + c0;
            float bx = 0.f, by = 0.f;
            if (bias) { bx = bias[n]; by = bias[n + 1]; }
            float vs[4] = {acc[mi][nj][0] + bx, acc[mi][nj][1] + by,
                           acc[mi][nj][2] + bx, acc[mi][nj][3] + by};
            if (EPI == 0) {
                *(float2*)(C + (m0 + r0) * (size_t)ldc + n) = make_float2(vs[0], vs[1]);
                *(float2*)(C + (m0 + r0 + 8) * (size_t)ldc + n) = make_float2(vs[2], vs[3]);
            } else {
                #pragma unroll
                for (int rr = 0; rr < 2; rr++) {
                    const size_t mrow = m0 + r0 + rr * 8;
                    const float vx = vs[rr * 2], vy = vs[rr * 2 + 1];
                    const bf16 hx = __float2bfloat16(vx);
                    const bf16 hy = __float2bfloat16(vy);
                    Chi[mrow * (size_t)ldc + n]     = hx;
                    Chi[mrow * (size_t)ldc + n + 1] = hy;
                    Clo[mrow * (size_t)ldc + n]     = __float2bfloat16(vx - __bfloat162float(hx));
                    Clo[mrow * (size_t)ldc + n + 1] = __float2bfloat16(vy - __bfloat162float(hy));
                }
            }
        }
    }
}

// ---------------- LSTM cell elementwise (proven) ----------------
__global__ void lstm_cell_kernel(const float* __restrict__ gx, float* __restrict__ out_t) {
    int idx = blockIdx.x * blockDim.x + threadIdx.x;
    if (idx >= BH) return;
    int b = idx / HH, hh = idx % HH;
    size_t base = (size_t)b * GG;
    float gi = gx[base + hh]          + g_gh[base + hh];
    float gf = gx[base + HH + hh]     + g_gh[base + HH + hh];
    float gg = gx[base + 2 * HH + hh] + g_gh[base + 2 * HH + hh];
    float go = gx[base + 3 * HH + hh] + g_gh[base + 3 * HH + hh];
    float i = 1.f / (1.f + expf(-gi));
    float f = 1.f / (1.f + expf(-gf));
    float g = tanhf(gg);
    float o = 1.f / (1.f + expf(-go));
    float cn = f * g_c[idx] + i * g;
    float hn = o * tanhf(cn);
    g_c[idx] = cn;
    bf16 hb = __float2bfloat16(hn);
    g_hhi[idx] = hb;
    g_hlo[idx] = __float2bfloat16(hn - __bfloat162float(hb));
    out_t[idx] = hn;
}

__global__ void copy_hc_kernel(const float* __restrict__ last_h, float* __restrict__ dst) {
    int i = blockIdx.x * blockDim.x + threadIdx.x;
    if (i < BH) { dst[i] = last_h[i]; dst[BH + i] = g_c[i]; }
}

// ---------------- launch ----------------
extern "C" void kernel_launch(void* const* d_in, const int* in_sizes, int n_in,
                              void* d_out, int out_size) {
    const float* inputs = (const float*)d_in[0];
    const float* h0     = (const float*)d_in[1];
    const float* c0     = (const float*)d_in[2];
    const float* W_emb  = (const float*)d_in[3];
    const float* b_emb  = (const float*)d_in[4];
    const float* W_ih   = (const float*)d_in[5];
    const float* W_hh   = (const float*)d_in[6];
    const float* b_ih   = (const float*)d_in[7];
    const float* b_hh   = (const float*)d_in[8];
    float* out = (float*)d_out;

    // Real device addresses of scratch globals (host-shadow trap otherwise).
    float *p_gx, *p_gh, *p_biasc;
    bf16 *p_xhi, *p_xlo, *p_wTh, *p_wTl, *p_wch, *p_wcl, *p_hhi, *p_hlo;
    bf16 *p_wihh, *p_wihl, *p_whhh, *p_whhl;
    cudaGetSymbolAddress((void**)&p_xhi,  g_xhi);
    cudaGetSymbolAddress((void**)&p_xlo,  g_xlo);
    cudaGetSymbolAddress((void**)&p_wTh,  g_wembT_hi);
    cudaGetSymbolAddress((void**)&p_wTl,  g_wembT_lo);
    cudaGetSymbolAddress((void**)&p_wch,  g_wc_hi);
    cudaGetSymbolAddress((void**)&p_wcl,  g_wc_lo);
    cudaGetSymbolAddress((void**)&p_biasc,g_bias_c);
    cudaGetSymbolAddress((void**)&p_gx,   g_gx);
    cudaGetSymbolAddress((void**)&p_gh,   g_gh);
    cudaGetSymbolAddress((void**)&p_hhi,  g_hhi);
    cudaGetSymbolAddress((void**)&p_hlo,  g_hlo);
    cudaGetSymbolAddress((void**)&p_wihh, g_wih_hi);
    cudaGetSymbolAddress((void**)&p_wihl, g_wih_lo);
    cudaGetSymbolAddress((void**)&p_whhh, g_whh_hi);
    cudaGetSymbolAddress((void**)&p_whhl, g_whh_lo);

    cudaFuncSetAttribute(mma_gemm_f<0>,
                         cudaFuncAttributeMaxDynamicSharedMemorySize, SMEM_F_BYTES);
    cudaFuncSetAttribute(mma_gemm_f<1>,
                         cudaFuncAttributeMaxDynamicSharedMemorySize, SMEM_F_BYTES);

    // prep
    reorder_pad_kernel<<<(M1 * KPAD + 255) / 256, 256>>>(inputs);
    transpose_wemb_kernel<<<(KPAD * HH + 255) / 256, 256>>>(W_emb);
    state_init_kernel<<<(BH + 255) / 256, 256>>>(h0, c0);
    decomp_bf16_kernel<<<(GG * HH + 255) / 256, 256>>>(W_ih, p_wihh, p_wihl, GG * HH);
    decomp_bf16_kernel<<<(GG * HH + 255) / 256, 256>>>(W_hh, p_whhh, p_whhl, GG * HH);
    bias_c_kernel<<<GG, 128>>>(W_ih, b_emb, b_ih, b_hh);

    // Wc = W_ih @ W_emb : [4096,1024] @ [1024,77->128]^T-form -> bf16 hi/lo [4096,128]
    mma_gemm_f<1><<<dim3(KPAD / 128, GG / 64), 128, SMEM_F_BYTES>>>(
        p_wihh, p_wihl, p_wTh, p_wTl, nullptr, nullptr, p_wch, p_wcl, HH, KPAD);

    // gx = x @ Wc^T + bias_c : [51200,128] @ [4096,128]^T -> [51200,4096]
    mma_gemm_f<0><<<dim3(GG / 128, M1 / 64), 128, SMEM_F_BYTES>>>(
        p_xhi, p_xlo, p_wch, p_wcl, p_biasc, p_gx, nullptr, nullptr, KPAD, GG);

    // recurrence: fused-load GEMM (256 CTAs, 3/SM) + separate cell (R8-proven)
    for (int t = 0; t < AA; t++) {
        mma_gemm_f<0><<<dim3(GG / 128, BB / 64), 128, SMEM_F_BYTES>>>(
            p_hhi, p_hlo, p_whhh, p_whhl, nullptr, p_gh, nullptr, nullptr, HH, GG);
        lstm_cell_kernel<<<(BH + 255) / 256, 256>>>(
            p_gx + (size_t)t * BB * GG, out + (size_t)t * BH);
    }

    // final (h, c) after output — only if the harness buffer includes them
    if (out_size >= (AA + 2) * BH) {
        copy_hc_kernel<<<(BH + 255) / 256, 256>>>(out + (size_t)(AA - 1) * BH,
                                                  out + (size_t)AA * BH);
    }
}